// round 12
// baseline (speedup 1.0000x reference)
#include <cuda_runtime.h>
#include <cuda_fp16.h>
#include <math_constants.h>
#include <cstdint>

// ---------------------------------------------------------------------------
// GraphTransformerModel: 2x TransformerConv (H=4, C=32, concat=False) + Linear
// N=50000, E=800000, D=128, HID=32, OUT=40
// Round 12: x8-deep attention gather (8 LDG.128 in flight per lane).
// KV row layout (256 halves): lane l owns halves [l*8, l*8+8):
//   [l*8 .. l*8+3] = K channels l*4..l*4+3,  [l*8+4 .. l*8+7] = V channels.
// ---------------------------------------------------------------------------

#define NMAX 50000
#define EMAX 800000
#define HEADS 4
#define CPH 32
#define FDIM 128
#define OUTC 40
#define SCAN_B 256

// ---- static device scratch ----
__device__ __half g_Q[NMAX * FDIM];
__device__ __half g_KV[(size_t)NMAX * 256];
__device__ float  g_skip[NMAX * CPH];
__device__ float  g_h1[NMAX * CPH];
__device__ int    g_csr_src[EMAX];
__device__ int    g_deg[NMAX];
__device__ int    g_off[NMAX];
__device__ int    g_cur[NMAX];
__device__ int    g_bsum[SCAN_B];
__device__ int    g_boff[SCAN_B];
__device__ int    g_is32;

// ---------------------------------------------------------------------------
// Fused QKV+skip HMMA GEMM, double-buffered B staging (unchanged round 11).
// ---------------------------------------------------------------------------
#define LDH 24   // B smem row halves (16 data + 8 pad) -> 12 u32

__device__ __forceinline__ void mma16816(float* d, const uint32_t* a,
                                         const uint32_t* b) {
    asm volatile(
        "mma.sync.aligned.m16n8k16.row.col.f32.f16.f16.f32 "
        "{%0,%1,%2,%3}, {%4,%5,%6,%7}, {%8,%9}, {%0,%1,%2,%3};"
        : "+f"(d[0]), "+f"(d[1]), "+f"(d[2]), "+f"(d[3])
        : "r"(a[0]), "r"(a[1]), "r"(a[2]), "r"(a[3]), "r"(b[0]), "r"(b[1]));
}

__global__ __launch_bounds__(256)
void hmma_qkvs_kernel(const float* __restrict__ A,
                      const float* __restrict__ Wq, const float* __restrict__ Wk,
                      const float* __restrict__ Wv, const float* __restrict__ Ws,
                      const float* __restrict__ bq, const float* __restrict__ bk,
                      const float* __restrict__ bv, const float* __restrict__ bs,
                      __half* __restrict__ Cq, __half* __restrict__ CKV,
                      float* __restrict__ Cs,
                      int rowbase, int N, int Kdim) {
    __shared__ __half sA[128 * 136];        // Kdim<=128 (+8 pad)
    __shared__ __half sB[2][128 * LDH];

    const int tid  = threadIdx.x;
    const int wid  = tid >> 5;
    const int lane = tid & 31;
    const int wm   = wid >> 2;
    const int wn   = wid & 3;
    const int row0 = rowbase + blockIdx.x * 128;
    const int lr   = lane >> 2;
    const int lc   = lane & 3;

    const int ldwh  = Kdim + 8;
    const int ldw32 = ldwh >> 1;
    const uint32_t* sA32 = (const uint32_t*)sA;

    // stage FULL A tile once: 128 rows x Kdim, fp32 -> fp16
    {
        const int kd4 = Kdim >> 2;
        for (int idx = tid; idx < 128 * kd4; idx += 256) {
            int r  = idx / kd4;
            int c4 = idx - r * kd4;
            int gr = min(row0 + r, N - 1);
            float4 a = *(const float4*)(A + (size_t)gr * Kdim + c4 * 4);
            __half2* dst = (__half2*)(sA + r * ldwh) + c4 * 2;
            dst[0] = __floats2half2_rn(a.x, a.y);
            dst[1] = __floats2half2_rn(a.z, a.w);
        }
    }

    const int nsteps = Kdim >> 4;

    #pragma unroll 1
    for (int m = 0; m < 4; m++) {
        const float* W;
        const float* bias;
        int Mcols;
        if (m == 0)      { W = Wq; bias = bq; Mcols = 128; }
        else if (m == 1) { W = Wk; bias = bk; Mcols = 128; }
        else if (m == 2) { W = Wv; bias = bv; Mcols = 128; }
        else             { W = Ws; bias = bs; Mcols = 32;  }

        float acc[4][4][4] = {};
        const int nb4   = Mcols * 4;
        const int mc4   = Mcols >> 2;

        __syncthreads();
        for (int idx = tid; idx < nb4; idx += 256) {
            int kk = idx / mc4;
            int n4 = idx - kk * mc4;
            float4 w = *(const float4*)(W + (size_t)kk * Mcols + n4 * 4);
            __half* d = sB[0];
            d[(n4 * 4 + 0) * LDH + kk] = __float2half_rn(w.x);
            d[(n4 * 4 + 1) * LDH + kk] = __float2half_rn(w.y);
            d[(n4 * 4 + 2) * LDH + kk] = __float2half_rn(w.z);
            d[(n4 * 4 + 3) * LDH + kk] = __float2half_rn(w.w);
        }
        __syncthreads();

        int cur = 0;
        for (int step = 0; step < nsteps; step++) {
            const int kw0 = step << 3;
            float4 wreg[2];
            int pk[2], pn[2], npre = 0;
            if (step + 1 < nsteps) {
                const int k0n = (step + 1) << 4;
                for (int idx = tid; idx < nb4; idx += 256) {
                    int kk = idx / mc4;
                    int n4 = idx - kk * mc4;
                    wreg[npre] = *(const float4*)(W + (size_t)(k0n + kk) * Mcols + n4 * 4);
                    pk[npre] = kk; pn[npre] = n4;
                    npre++;
                }
            }

            const uint32_t* sBc = (const uint32_t*)sB[cur];
            if (m < 3) {
                uint32_t af[4][4], bf[4][2];
                #pragma unroll
                for (int mt = 0; mt < 4; mt++) {
                    int rm = wm * 64 + mt * 16;
                    #pragma unroll
                    for (int j = 0; j < 4; j++)
                        af[mt][j] = sA32[(rm + lr + (j & 1) * 8) * ldw32 +
                                         kw0 + lc + (j >> 1) * 4];
                }
                #pragma unroll
                for (int nt = 0; nt < 4; nt++) {
                    int cn = wn * 32 + nt * 8;
                    bf[nt][0] = sBc[(cn + lr) * 12 + lc];
                    bf[nt][1] = sBc[(cn + lr) * 12 + lc + 4];
                }
                #pragma unroll
                for (int mt = 0; mt < 4; mt++)
                    #pragma unroll
                    for (int nt = 0; nt < 4; nt++)
                        mma16816(acc[mt][nt], af[mt], bf[nt]);
            } else {
                uint32_t af[4], bf[4][2];
                int rm = wid * 16;
                #pragma unroll
                for (int j = 0; j < 4; j++)
                    af[j] = sA32[(rm + lr + (j & 1) * 8) * ldw32 +
                                 kw0 + lc + (j >> 1) * 4];
                #pragma unroll
                for (int nt = 0; nt < 4; nt++) {
                    int cn = nt * 8;
                    bf[nt][0] = sBc[(cn + lr) * 12 + lc];
                    bf[nt][1] = sBc[(cn + lr) * 12 + lc + 4];
                }
                #pragma unroll
                for (int nt = 0; nt < 4; nt++)
                    mma16816(acc[0][nt], af, bf[nt]);
            }

            if (step + 1 < nsteps) {
                __half* d = sB[cur ^ 1];
                for (int p = 0; p < npre; p++) {
                    d[(pn[p] * 4 + 0) * LDH + pk[p]] = __float2half_rn(wreg[p].x);
                    d[(pn[p] * 4 + 1) * LDH + pk[p]] = __float2half_rn(wreg[p].y);
                    d[(pn[p] * 4 + 2) * LDH + pk[p]] = __float2half_rn(wreg[p].z);
                    d[(pn[p] * 4 + 3) * LDH + pk[p]] = __float2half_rn(wreg[p].w);
                }
                __syncthreads();
                cur ^= 1;
            }
        }

        // ---- epilogue ----
        if (m == 0) {
            #pragma unroll
            for (int mt = 0; mt < 4; mt++) {
                int r0 = row0 + wm * 64 + mt * 16 + lr;
                #pragma unroll
                for (int nt = 0; nt < 4; nt++) {
                    int gc = wn * 32 + nt * 8 + lc * 2;
                    float bx = bias[gc], by = bias[gc + 1];
                    if (r0 < N)
                        *(__half2*)(Cq + (size_t)r0 * 128 + gc) =
                            __floats2half2_rn(acc[mt][nt][0] + bx, acc[mt][nt][1] + by);
                    if (r0 + 8 < N)
                        *(__half2*)(Cq + (size_t)(r0 + 8) * 128 + gc) =
                            __floats2half2_rn(acc[mt][nt][2] + bx, acc[mt][nt][3] + by);
                }
            }
        } else if (m < 3) {
            // interleaved KV layout: channel c -> (c>>2)*8 + (c&3) (+4 for V)
            const int voff = (m == 2) ? 4 : 0;
            #pragma unroll
            for (int mt = 0; mt < 4; mt++) {
                int r0 = row0 + wm * 64 + mt * 16 + lr;
                #pragma unroll
                for (int nt = 0; nt < 4; nt++) {
                    int gc = wn * 32 + nt * 8 + lc * 2;
                    int ioff = ((gc >> 2) << 3) + (gc & 3) + voff;
                    float bx = bias[gc], by = bias[gc + 1];
                    if (r0 < N)
                        *(__half2*)(CKV + (size_t)r0 * 256 + ioff) =
                            __floats2half2_rn(acc[mt][nt][0] + bx, acc[mt][nt][1] + by);
                    if (r0 + 8 < N)
                        *(__half2*)(CKV + (size_t)(r0 + 8) * 256 + ioff) =
                            __floats2half2_rn(acc[mt][nt][2] + bx, acc[mt][nt][3] + by);
                }
            }
        } else {
            int r0 = row0 + wid * 16 + lr;
            #pragma unroll
            for (int nt = 0; nt < 4; nt++) {
                int gc = nt * 8 + lc * 2;
                float bx = bias[gc], by = bias[gc + 1];
                if (r0 < N)
                    *(float2*)(Cs + (size_t)r0 * 32 + gc) =
                        make_float2(acc[0][nt][0] + bx, acc[0][nt][1] + by);
                if (r0 + 8 < N)
                    *(float2*)(Cs + (size_t)(r0 + 8) * 32 + gc) =
                        make_float2(acc[0][nt][2] + bx, acc[0][nt][3] + by);
            }
        }
    }
}

// ---------------------------------------------------------------------------
// Preprocessing (unchanged)
// ---------------------------------------------------------------------------
__global__ void init_pre_kernel(int N) {
    int i = blockIdx.x * blockDim.x + threadIdx.x;
    if (i == 0) g_is32 = 0;
    if (i < N) g_deg[i] = 0;
}

__global__ void detect_dtype_kernel(const uint2* __restrict__ w, int npairs) {
    int i = blockIdx.x * blockDim.x + threadIdx.x;
    if (i < npairs && w[i].y != 0u) g_is32 = 1;
}

__global__ void hist_kernel(const void* __restrict__ ei, int E) {
    int e = blockIdx.x * blockDim.x + threadIdx.x;
    if (e >= E) return;
    int d;
    if (g_is32) d = ((const int*)ei)[E + e];
    else        d = (int)((const long long*)ei)[E + e];
    atomicAdd(&g_deg[d], 1);
}

__global__ __launch_bounds__(SCAN_B)
void scan_p1_kernel(int N) {
    __shared__ int sh[SCAN_B];
    int t = threadIdx.x;
    int i = blockIdx.x * SCAN_B + t;
    int v = (i < N) ? g_deg[i] : 0;
    sh[t] = v;
    __syncthreads();
    #pragma unroll
    for (int s = SCAN_B / 2; s > 0; s >>= 1) {
        if (t < s) sh[t] += sh[t + s];
        __syncthreads();
    }
    if (t == 0) g_bsum[blockIdx.x] = sh[0];
}

__global__ __launch_bounds__(SCAN_B)
void scan_p2_kernel(int NB) {
    __shared__ int sh[SCAN_B];
    int t = threadIdx.x;
    int v = (t < NB) ? g_bsum[t] : 0;
    sh[t] = v;
    __syncthreads();
    #pragma unroll
    for (int d = 1; d < SCAN_B; d <<= 1) {
        int u = (t >= d) ? sh[t - d] : 0;
        __syncthreads();
        sh[t] += u;
        __syncthreads();
    }
    if (t < NB) g_boff[t] = sh[t] - v;
}

__global__ __launch_bounds__(SCAN_B)
void scan_p3_kernel(int N) {
    __shared__ int sh[SCAN_B];
    int t = threadIdx.x;
    int i = blockIdx.x * SCAN_B + t;
    int v = (i < N) ? g_deg[i] : 0;
    sh[t] = v;
    __syncthreads();
    #pragma unroll
    for (int d = 1; d < SCAN_B; d <<= 1) {
        int u = (t >= d) ? sh[t - d] : 0;
        __syncthreads();
        sh[t] += u;
        __syncthreads();
    }
    if (i < N) {
        int excl = sh[t] - v + g_boff[blockIdx.x];
        g_off[i] = excl;
        g_cur[i] = excl;
    }
}

__global__ void scatter_kernel(const void* __restrict__ ei, int E) {
    int e = blockIdx.x * blockDim.x + threadIdx.x;
    if (e >= E) return;
    int s, d;
    if (g_is32) {
        const int* p = (const int*)ei;
        s = p[e];
        d = p[E + e];
    } else {
        const long long* p = (const long long*)ei;
        s = (int)p[e];
        d = (int)p[E + e];
    }
    int pidx = atomicAdd(&g_cur[d], 1);
    g_csr_src[pidx] = s;
}

// ---------------------------------------------------------------------------
// Single-pass fused attention, fp16 Q + interleaved fp16 KV.
// x8-unrolled gather: 8 LDG.128 issued back-to-back per lane (MLP=8).
// Node range [nbase, nend). do_cls=1: classifier fused into epilogue.
// ---------------------------------------------------------------------------
__device__ __forceinline__ float4 unpack_lo(const uint4& r) {
    float2 a = __half22float2(*(const __half2*)&r.x);
    float2 b = __half22float2(*(const __half2*)&r.y);
    return make_float4(a.x, a.y, b.x, b.y);
}
__device__ __forceinline__ float4 unpack_hi(const uint4& r) {
    float2 a = __half22float2(*(const __half2*)&r.z);
    float2 b = __half22float2(*(const __half2*)&r.w);
    return make_float4(a.x, a.y, b.x, b.y);
}

__global__ __launch_bounds__(256)
void attn_fused_kernel(const __half* __restrict__ Q, const __half* __restrict__ KV,
                       const float* __restrict__ skip,
                       float* __restrict__ out,
                       const float* __restrict__ wc, const float* __restrict__ bc,
                       int do_cls, int nbase, int nend, int N, int E) {
    __shared__ float s_wc[CPH * OUTC];
    __shared__ float s_bc[OUTC];
    __shared__ float s_h[8][CPH];

    const int tid  = threadIdx.x;
    const int wid  = tid >> 5;
    const int lane = tid & 31;

    if (do_cls) {
        for (int i = tid; i < CPH * OUTC; i += 256) s_wc[i] = wc[i];
        if (tid < OUTC) s_bc[tid] = bc[tid];
        __syncthreads();
    }

    int n = nbase + ((blockIdx.x * blockDim.x + tid) >> 5);
    if (n >= nend) return;
    const int beg = g_off[n];
    const int end = (n + 1 < N) ? g_off[n + 1] : E;

    // fp16 Q: 4 halves per lane
    float4 q;
    {
        uint2 u = *(const uint2*)(Q + (size_t)n * FDIM + lane * 4);
        float2 f0 = __half22float2(*(const __half2*)&u.x);
        float2 f1 = __half22float2(*(const __half2*)&u.y);
        q = make_float4(f0.x, f0.y, f1.x, f1.y);
    }

    float den = 0.f;
    float a0 = 0.f, a1 = 0.f, a2 = 0.f, a3 = 0.f;
    const float scale = 0.17677669529663687f;  // 1/sqrt(32)

    for (int base = beg; base < end; base += 32) {
        int myidx = (base + lane < end) ? g_csr_src[base + lane] : 0;
        int rem = end - base;
        int cnt = rem < 32 ? rem : 32;
        int j = 0;
        // x8-deep: shuffle 8 indices, issue 8 LDG.128, then compute
        for (; j + 7 < cnt; j += 8) {
            uint4 r[8];
            {
                int s[8];
                #pragma unroll
                for (int u = 0; u < 8; u++)
                    s[u] = __shfl_sync(0xffffffffu, myidx, j + u);
                #pragma unroll
                for (int u = 0; u < 8; u++)
                    r[u] = *(const uint4*)(KV + (size_t)s[u] * 256 + lane * 8);
            }
            float d[8];
            #pragma unroll
            for (int u = 0; u < 8; u++) {
                float4 k = unpack_lo(r[u]);
                d[u] = q.x * k.x + q.y * k.y + q.z * k.z + q.w * k.w;
            }
            #pragma unroll
            for (int u = 0; u < 8; u++) d[u] += __shfl_xor_sync(0xffffffffu, d[u], 4);
            #pragma unroll
            for (int u = 0; u < 8; u++) d[u] += __shfl_xor_sync(0xffffffffu, d[u], 2);
            #pragma unroll
            for (int u = 0; u < 8; u++) d[u] += __shfl_xor_sync(0xffffffffu, d[u], 1);
            float wsum = 0.f;
            #pragma unroll
            for (int u = 0; u < 8; u++) {
                float w = __expf(d[u] * scale);
                d[u] = w;          // reuse as weight
                wsum += w;
            }
            den += wsum;
            #pragma unroll
            for (int u = 0; u < 8; u++) {
                float4 v = unpack_hi(r[u]);
                a0 = fmaf(d[u], v.x, a0);
                a1 = fmaf(d[u], v.y, a1);
                a2 = fmaf(d[u], v.z, a2);
                a3 = fmaf(d[u], v.w, a3);
            }
        }
        for (; j < cnt; j++) {
            int s0 = __shfl_sync(0xffffffffu, myidx, j);
            uint4 r0 = *(const uint4*)(KV + (size_t)s0 * 256 + lane * 8);
            float4 k0 = unpack_lo(r0);
            float4 v0 = unpack_hi(r0);
            float d0 = q.x * k0.x + q.y * k0.y + q.z * k0.z + q.w * k0.w;
            d0 += __shfl_xor_sync(0xffffffffu, d0, 4);
            d0 += __shfl_xor_sync(0xffffffffu, d0, 2);
            d0 += __shfl_xor_sync(0xffffffffu, d0, 1);
            float w0 = __expf(d0 * scale);
            den += w0;
            a0 = fmaf(w0, v0.x, a0);
            a1 = fmaf(w0, v0.y, a1);
            a2 = fmaf(w0, v0.z, a2);
            a3 = fmaf(w0, v0.w, a3);
        }
    }

    const float rden = 1.f / (den + 1e-16f);
    a0 *= rden; a1 *= rden; a2 *= rden; a3 *= rden;

    // head mean: sum over 4 heads (lanes l, l^8, l^16, l^24 share channels)
    #pragma unroll
    for (int dd = 8; dd <= 16; dd <<= 1) {
        a0 += __shfl_xor_sync(0xffffffffu, a0, dd);
        a1 += __shfl_xor_sync(0xffffffffu, a1, dd);
        a2 += __shfl_xor_sync(0xffffffffu, a2, dd);
        a3 += __shfl_xor_sync(0xffffffffu, a3, dd);
    }

    if (lane < 8) {
        float4 sk = *(const float4*)(skip + (size_t)n * CPH + lane * 4);
        float4 o;
        o.x = fmaxf(a0 * 0.25f + sk.x, 0.f);
        o.y = fmaxf(a1 * 0.25f + sk.y, 0.f);
        o.z = fmaxf(a2 * 0.25f + sk.z, 0.f);
        o.w = fmaxf(a3 * 0.25f + sk.w, 0.f);
        if (!do_cls) {
            *(float4*)(out + (size_t)n * CPH + lane * 4) = o;
        } else {
            *(float4*)&s_h[wid][lane * 4] = o;
        }
    }

    if (do_cls) {
        __syncwarp();
        const float* h = s_h[wid];
        int c2 = 32 + (lane & 7);
        float acc1 = s_bc[lane];
        float acc2 = s_bc[c2];
        #pragma unroll 8
        for (int j = 0; j < CPH; j++) {
            float hv = h[j];
            acc1 = fmaf(hv, s_wc[j * OUTC + lane], acc1);
            acc2 = fmaf(hv, s_wc[j * OUTC + c2], acc2);
        }
        out[(size_t)n * OUTC + lane] = acc1;
        if (lane < 8) out[(size_t)n * OUTC + c2] = acc2;
    }
}

// ---------------------------------------------------------------------------
// Host orchestration (unchanged from round 11)
// ---------------------------------------------------------------------------
static inline unsigned int ceil_div(unsigned int a, unsigned int b) { return (a + b - 1) / b; }

extern "C" void kernel_launch(void* const* d_in, const int* in_sizes, int n_in,
                              void* d_out, int out_size) {
    const float* x   = (const float*)d_in[0];
    const void*  ei  = d_in[1];
    const float* wq1 = (const float*)d_in[2];
    const float* bq1 = (const float*)d_in[3];
    const float* wk1 = (const float*)d_in[4];
    const float* bk1 = (const float*)d_in[5];
    const float* wv1 = (const float*)d_in[6];
    const float* bv1 = (const float*)d_in[7];
    const float* ws1 = (const float*)d_in[8];
    const float* bs1 = (const float*)d_in[9];
    const float* wq2 = (const float*)d_in[10];
    const float* bq2 = (const float*)d_in[11];
    const float* wk2 = (const float*)d_in[12];
    const float* bk2 = (const float*)d_in[13];
    const float* wv2 = (const float*)d_in[14];
    const float* bv2 = (const float*)d_in[15];
    const float* ws2 = (const float*)d_in[16];
    const float* bs2 = (const float*)d_in[17];
    const float* wc  = (const float*)d_in[18];
    const float* bc  = (const float*)d_in[19];

    const int N = in_sizes[0] / FDIM;   // x is [N,128]
    const int E = in_sizes[1] / 2;      // edge_index is [2,E]

    float  *skipp, *h1p;
    __half *Qp, *KVp;
    cudaGetSymbolAddress((void**)&Qp,    g_Q);
    cudaGetSymbolAddress((void**)&KVp,   g_KV);
    cudaGetSymbolAddress((void**)&skipp, g_skip);
    cudaGetSymbolAddress((void**)&h1p,   g_h1);

    static cudaStream_t s_pre = nullptr;
    static cudaEvent_t  ev_fork = nullptr, ev_join = nullptr;
    static cudaEvent_t  ev_a0 = nullptr, ev_g0 = nullptr;
    if (s_pre == nullptr) {
        cudaStreamCreate(&s_pre);
        cudaEventCreateWithFlags(&ev_fork, cudaEventDisableTiming);
        cudaEventCreateWithFlags(&ev_join, cudaEventDisableTiming);
        cudaEventCreateWithFlags(&ev_a0, cudaEventDisableTiming);
        cudaEventCreateWithFlags(&ev_g0, cudaEventDisableTiming);
    }

    const int NB = (N + SCAN_B - 1) / SCAN_B;
    int Nh = ((N / 2 + 127) / 128) * 128;
    if (Nh > N) Nh = N;
    const int detect_pairs = (E < 65536) ? E : 65536;

    // fork: CSR build on s_pre, concurrent with layer-1 GEMM
    cudaEventRecord(ev_fork, 0);
    cudaStreamWaitEvent(s_pre, ev_fork, 0);
    init_pre_kernel<<<ceil_div((unsigned)N, 256u), 256, 0, s_pre>>>(N);
    detect_dtype_kernel<<<ceil_div((unsigned)detect_pairs, 256u), 256, 0, s_pre>>>(
        (const uint2*)ei, detect_pairs);
    hist_kernel<<<ceil_div((unsigned)E, 256u), 256, 0, s_pre>>>(ei, E);
    scan_p1_kernel<<<NB, SCAN_B, 0, s_pre>>>(N);
    scan_p2_kernel<<<1, SCAN_B, 0, s_pre>>>(NB);
    scan_p3_kernel<<<NB, SCAN_B, 0, s_pre>>>(N);
    scatter_kernel<<<ceil_div((unsigned)E, 256u), 256, 0, s_pre>>>(ei, E);
    cudaEventRecord(ev_join, s_pre);

    hmma_qkvs_kernel<<<ceil_div((unsigned)N, 128u), 256>>>(
        x, wq1, wk1, wv1, ws1, bq1, bk1, bv1, bs1, Qp, KVp, skipp, 0, N, FDIM);

    cudaStreamWaitEvent(0, ev_join, 0);

    attn_fused_kernel<<<ceil_div((unsigned)Nh, 8u), 256>>>(
        Qp, KVp, skipp, h1p, wc, bc, 0, 0, Nh, N, E);
    cudaEventRecord(ev_a0, 0);

    cudaStreamWaitEvent(s_pre, ev_a0, 0);
    hmma_qkvs_kernel<<<ceil_div((unsigned)Nh, 128u), 256, 0, s_pre>>>(
        h1p, wq2, wk2, wv2, ws2, bq2, bk2, bv2, bs2, Qp, KVp, skipp, 0, N, CPH);
    cudaEventRecord(ev_g0, s_pre);

    if (Nh < N)
        attn_fused_kernel<<<ceil_div((unsigned)(N - Nh), 8u), 256>>>(
            Qp, KVp, skipp, h1p, wc, bc, 0, Nh, N, N, E);

    if (Nh < N)
        hmma_qkvs_kernel<<<ceil_div((unsigned)(N - Nh), 128u), 256>>>(
            h1p, wq2, wk2, wv2, ws2, bq2, bk2, bv2, bs2, Qp, KVp, skipp, Nh, N, CPH);

    cudaStreamWaitEvent(0, ev_g0, 0);
    attn_fused_kernel<<<ceil_div((unsigned)N, 8u), 256>>>(
        Qp, KVp, skipp, (float*)d_out, wc, bc, 1, 0, N, N, E);
}

// round 13
// speedup vs baseline: 1.0470x; 1.0470x over previous
#include <cuda_runtime.h>
#include <cuda_fp16.h>
#include <math_constants.h>
#include <cstdint>

// ---------------------------------------------------------------------------
// GraphTransformerModel: 2x TransformerConv (H=4, C=32, concat=False) + Linear
// N=50000, E=800000, D=128, HID=32, OUT=40
// Round 13: revert gather to x4 (x8 regressed); h1 stored fp16 (straight-copy
// A staging in layer-2 GEMM, half the h1 traffic).
// KV row layout (256 halves): lane l owns halves [l*8, l*8+8):
//   [l*8 .. l*8+3] = K channels l*4..l*4+3,  [l*8+4 .. l*8+7] = V channels.
// ---------------------------------------------------------------------------

#define NMAX 50000
#define EMAX 800000
#define HEADS 4
#define CPH 32
#define FDIM 128
#define OUTC 40
#define SCAN_B 256

// ---- static device scratch ----
__device__ __half g_Q[NMAX * FDIM];
__device__ __half g_KV[(size_t)NMAX * 256];
__device__ float  g_skip[NMAX * CPH];
__device__ __half g_h1[NMAX * CPH];
__device__ int    g_csr_src[EMAX];
__device__ int    g_deg[NMAX];
__device__ int    g_off[NMAX];
__device__ int    g_cur[NMAX];
__device__ int    g_bsum[SCAN_B];
__device__ int    g_boff[SCAN_B];
__device__ int    g_is32;

// ---------------------------------------------------------------------------
// Fused QKV+skip HMMA GEMM, double-buffered B staging.
// A input either fp32 (a_half=0) or fp16 (a_half=1, straight copy staging).
// ---------------------------------------------------------------------------
#define LDH 24   // B smem row halves (16 data + 8 pad) -> 12 u32

__device__ __forceinline__ void mma16816(float* d, const uint32_t* a,
                                         const uint32_t* b) {
    asm volatile(
        "mma.sync.aligned.m16n8k16.row.col.f32.f16.f16.f32 "
        "{%0,%1,%2,%3}, {%4,%5,%6,%7}, {%8,%9}, {%0,%1,%2,%3};"
        : "+f"(d[0]), "+f"(d[1]), "+f"(d[2]), "+f"(d[3])
        : "r"(a[0]), "r"(a[1]), "r"(a[2]), "r"(a[3]), "r"(b[0]), "r"(b[1]));
}

__global__ __launch_bounds__(256)
void hmma_qkvs_kernel(const void* __restrict__ A, int a_half,
                      const float* __restrict__ Wq, const float* __restrict__ Wk,
                      const float* __restrict__ Wv, const float* __restrict__ Ws,
                      const float* __restrict__ bq, const float* __restrict__ bk,
                      const float* __restrict__ bv, const float* __restrict__ bs,
                      __half* __restrict__ Cq, __half* __restrict__ CKV,
                      float* __restrict__ Cs,
                      int rowbase, int N, int Kdim) {
    __shared__ __half sA[128 * 136];        // Kdim<=128 (+8 pad)
    __shared__ __half sB[2][128 * LDH];

    const int tid  = threadIdx.x;
    const int wid  = tid >> 5;
    const int lane = tid & 31;
    const int wm   = wid >> 2;
    const int wn   = wid & 3;
    const int row0 = rowbase + blockIdx.x * 128;
    const int lr   = lane >> 2;
    const int lc   = lane & 3;

    const int ldwh  = Kdim + 8;
    const int ldw32 = ldwh >> 1;
    const uint32_t* sA32 = (const uint32_t*)sA;

    // stage FULL A tile once: 128 rows x Kdim
    {
        const int kd4 = Kdim >> 2;
        for (int idx = tid; idx < 128 * kd4; idx += 256) {
            int r  = idx / kd4;
            int c4 = idx - r * kd4;
            int gr = min(row0 + r, N - 1);
            __half2* dst = (__half2*)(sA + r * ldwh) + c4 * 2;
            if (a_half) {
                uint2 u = *(const uint2*)((const __half*)A + (size_t)gr * Kdim + c4 * 4);
                dst[0] = *(__half2*)&u.x;
                dst[1] = *(__half2*)&u.y;
            } else {
                float4 a = *(const float4*)((const float*)A + (size_t)gr * Kdim + c4 * 4);
                dst[0] = __floats2half2_rn(a.x, a.y);
                dst[1] = __floats2half2_rn(a.z, a.w);
            }
        }
    }

    const int nsteps = Kdim >> 4;

    #pragma unroll 1
    for (int m = 0; m < 4; m++) {
        const float* W;
        const float* bias;
        int Mcols;
        if (m == 0)      { W = Wq; bias = bq; Mcols = 128; }
        else if (m == 1) { W = Wk; bias = bk; Mcols = 128; }
        else if (m == 2) { W = Wv; bias = bv; Mcols = 128; }
        else             { W = Ws; bias = bs; Mcols = 32;  }

        float acc[4][4][4] = {};
        const int nb4   = Mcols * 4;
        const int mc4   = Mcols >> 2;

        __syncthreads();
        for (int idx = tid; idx < nb4; idx += 256) {
            int kk = idx / mc4;
            int n4 = idx - kk * mc4;
            float4 w = *(const float4*)(W + (size_t)kk * Mcols + n4 * 4);
            __half* d = sB[0];
            d[(n4 * 4 + 0) * LDH + kk] = __float2half_rn(w.x);
            d[(n4 * 4 + 1) * LDH + kk] = __float2half_rn(w.y);
            d[(n4 * 4 + 2) * LDH + kk] = __float2half_rn(w.z);
            d[(n4 * 4 + 3) * LDH + kk] = __float2half_rn(w.w);
        }
        __syncthreads();

        int cur = 0;
        for (int step = 0; step < nsteps; step++) {
            const int kw0 = step << 3;
            float4 wreg[2];
            int pk[2], pn[2], npre = 0;
            if (step + 1 < nsteps) {
                const int k0n = (step + 1) << 4;
                for (int idx = tid; idx < nb4; idx += 256) {
                    int kk = idx / mc4;
                    int n4 = idx - kk * mc4;
                    wreg[npre] = *(const float4*)(W + (size_t)(k0n + kk) * Mcols + n4 * 4);
                    pk[npre] = kk; pn[npre] = n4;
                    npre++;
                }
            }

            const uint32_t* sBc = (const uint32_t*)sB[cur];
            if (m < 3) {
                uint32_t af[4][4], bf[4][2];
                #pragma unroll
                for (int mt = 0; mt < 4; mt++) {
                    int rm = wm * 64 + mt * 16;
                    #pragma unroll
                    for (int j = 0; j < 4; j++)
                        af[mt][j] = sA32[(rm + lr + (j & 1) * 8) * ldw32 +
                                         kw0 + lc + (j >> 1) * 4];
                }
                #pragma unroll
                for (int nt = 0; nt < 4; nt++) {
                    int cn = wn * 32 + nt * 8;
                    bf[nt][0] = sBc[(cn + lr) * 12 + lc];
                    bf[nt][1] = sBc[(cn + lr) * 12 + lc + 4];
                }
                #pragma unroll
                for (int mt = 0; mt < 4; mt++)
                    #pragma unroll
                    for (int nt = 0; nt < 4; nt++)
                        mma16816(acc[mt][nt], af[mt], bf[nt]);
            } else {
                uint32_t af[4], bf[4][2];
                int rm = wid * 16;
                #pragma unroll
                for (int j = 0; j < 4; j++)
                    af[j] = sA32[(rm + lr + (j & 1) * 8) * ldw32 +
                                 kw0 + lc + (j >> 1) * 4];
                #pragma unroll
                for (int nt = 0; nt < 4; nt++) {
                    int cn = nt * 8;
                    bf[nt][0] = sBc[(cn + lr) * 12 + lc];
                    bf[nt][1] = sBc[(cn + lr) * 12 + lc + 4];
                }
                #pragma unroll
                for (int nt = 0; nt < 4; nt++)
                    mma16816(acc[0][nt], af, bf[nt]);
            }

            if (step + 1 < nsteps) {
                __half* d = sB[cur ^ 1];
                for (int p = 0; p < npre; p++) {
                    d[(pn[p] * 4 + 0) * LDH + pk[p]] = __float2half_rn(wreg[p].x);
                    d[(pn[p] * 4 + 1) * LDH + pk[p]] = __float2half_rn(wreg[p].y);
                    d[(pn[p] * 4 + 2) * LDH + pk[p]] = __float2half_rn(wreg[p].z);
                    d[(pn[p] * 4 + 3) * LDH + pk[p]] = __float2half_rn(wreg[p].w);
                }
                __syncthreads();
                cur ^= 1;
            }
        }

        // ---- epilogue ----
        if (m == 0) {
            #pragma unroll
            for (int mt = 0; mt < 4; mt++) {
                int r0 = row0 + wm * 64 + mt * 16 + lr;
                #pragma unroll
                for (int nt = 0; nt < 4; nt++) {
                    int gc = wn * 32 + nt * 8 + lc * 2;
                    float bx = bias[gc], by = bias[gc + 1];
                    if (r0 < N)
                        *(__half2*)(Cq + (size_t)r0 * 128 + gc) =
                            __floats2half2_rn(acc[mt][nt][0] + bx, acc[mt][nt][1] + by);
                    if (r0 + 8 < N)
                        *(__half2*)(Cq + (size_t)(r0 + 8) * 128 + gc) =
                            __floats2half2_rn(acc[mt][nt][2] + bx, acc[mt][nt][3] + by);
                }
            }
        } else if (m < 3) {
            // interleaved KV layout: channel c -> (c>>2)*8 + (c&3) (+4 for V)
            const int voff = (m == 2) ? 4 : 0;
            #pragma unroll
            for (int mt = 0; mt < 4; mt++) {
                int r0 = row0 + wm * 64 + mt * 16 + lr;
                #pragma unroll
                for (int nt = 0; nt < 4; nt++) {
                    int gc = wn * 32 + nt * 8 + lc * 2;
                    int ioff = ((gc >> 2) << 3) + (gc & 3) + voff;
                    float bx = bias[gc], by = bias[gc + 1];
                    if (r0 < N)
                        *(__half2*)(CKV + (size_t)r0 * 256 + ioff) =
                            __floats2half2_rn(acc[mt][nt][0] + bx, acc[mt][nt][1] + by);
                    if (r0 + 8 < N)
                        *(__half2*)(CKV + (size_t)(r0 + 8) * 256 + ioff) =
                            __floats2half2_rn(acc[mt][nt][2] + bx, acc[mt][nt][3] + by);
                }
            }
        } else {
            int r0 = row0 + wid * 16 + lr;
            #pragma unroll
            for (int nt = 0; nt < 4; nt++) {
                int gc = nt * 8 + lc * 2;
                float bx = bias[gc], by = bias[gc + 1];
                if (r0 < N)
                    *(float2*)(Cs + (size_t)r0 * 32 + gc) =
                        make_float2(acc[0][nt][0] + bx, acc[0][nt][1] + by);
                if (r0 + 8 < N)
                    *(float2*)(Cs + (size_t)(r0 + 8) * 32 + gc) =
                        make_float2(acc[0][nt][2] + bx, acc[0][nt][3] + by);
            }
        }
    }
}

// ---------------------------------------------------------------------------
// Preprocessing (unchanged)
// ---------------------------------------------------------------------------
__global__ void init_pre_kernel(int N) {
    int i = blockIdx.x * blockDim.x + threadIdx.x;
    if (i == 0) g_is32 = 0;
    if (i < N) g_deg[i] = 0;
}

__global__ void detect_dtype_kernel(const uint2* __restrict__ w, int npairs) {
    int i = blockIdx.x * blockDim.x + threadIdx.x;
    if (i < npairs && w[i].y != 0u) g_is32 = 1;
}

__global__ void hist_kernel(const void* __restrict__ ei, int E) {
    int e = blockIdx.x * blockDim.x + threadIdx.x;
    if (e >= E) return;
    int d;
    if (g_is32) d = ((const int*)ei)[E + e];
    else        d = (int)((const long long*)ei)[E + e];
    atomicAdd(&g_deg[d], 1);
}

__global__ __launch_bounds__(SCAN_B)
void scan_p1_kernel(int N) {
    __shared__ int sh[SCAN_B];
    int t = threadIdx.x;
    int i = blockIdx.x * SCAN_B + t;
    int v = (i < N) ? g_deg[i] : 0;
    sh[t] = v;
    __syncthreads();
    #pragma unroll
    for (int s = SCAN_B / 2; s > 0; s >>= 1) {
        if (t < s) sh[t] += sh[t + s];
        __syncthreads();
    }
    if (t == 0) g_bsum[blockIdx.x] = sh[0];
}

__global__ __launch_bounds__(SCAN_B)
void scan_p2_kernel(int NB) {
    __shared__ int sh[SCAN_B];
    int t = threadIdx.x;
    int v = (t < NB) ? g_bsum[t] : 0;
    sh[t] = v;
    __syncthreads();
    #pragma unroll
    for (int d = 1; d < SCAN_B; d <<= 1) {
        int u = (t >= d) ? sh[t - d] : 0;
        __syncthreads();
        sh[t] += u;
        __syncthreads();
    }
    if (t < NB) g_boff[t] = sh[t] - v;
}

__global__ __launch_bounds__(SCAN_B)
void scan_p3_kernel(int N) {
    __shared__ int sh[SCAN_B];
    int t = threadIdx.x;
    int i = blockIdx.x * SCAN_B + t;
    int v = (i < N) ? g_deg[i] : 0;
    sh[t] = v;
    __syncthreads();
    #pragma unroll
    for (int d = 1; d < SCAN_B; d <<= 1) {
        int u = (t >= d) ? sh[t - d] : 0;
        __syncthreads();
        sh[t] += u;
        __syncthreads();
    }
    if (i < N) {
        int excl = sh[t] - v + g_boff[blockIdx.x];
        g_off[i] = excl;
        g_cur[i] = excl;
    }
}

__global__ void scatter_kernel(const void* __restrict__ ei, int E) {
    int e = blockIdx.x * blockDim.x + threadIdx.x;
    if (e >= E) return;
    int s, d;
    if (g_is32) {
        const int* p = (const int*)ei;
        s = p[e];
        d = p[E + e];
    } else {
        const long long* p = (const long long*)ei;
        s = (int)p[e];
        d = (int)p[E + e];
    }
    int pidx = atomicAdd(&g_cur[d], 1);
    g_csr_src[pidx] = s;
}

// ---------------------------------------------------------------------------
// Single-pass fused attention, fp16 Q + interleaved fp16 KV, x4 gather.
// do_cls=0: writes fp16 h (out_h). do_cls=1: classifier fused, fp32 out.
// ---------------------------------------------------------------------------
__device__ __forceinline__ float4 unpack_lo(const uint4& r) {
    float2 a = __half22float2(*(const __half2*)&r.x);
    float2 b = __half22float2(*(const __half2*)&r.y);
    return make_float4(a.x, a.y, b.x, b.y);
}
__device__ __forceinline__ float4 unpack_hi(const uint4& r) {
    float2 a = __half22float2(*(const __half2*)&r.z);
    float2 b = __half22float2(*(const __half2*)&r.w);
    return make_float4(a.x, a.y, b.x, b.y);
}

__global__ __launch_bounds__(256)
void attn_fused_kernel(const __half* __restrict__ Q, const __half* __restrict__ KV,
                       const float* __restrict__ skip,
                       __half* __restrict__ out_h, float* __restrict__ out_f,
                       const float* __restrict__ wc, const float* __restrict__ bc,
                       int do_cls, int nbase, int nend, int N, int E) {
    __shared__ float s_wc[CPH * OUTC];
    __shared__ float s_bc[OUTC];
    __shared__ float s_h[8][CPH];

    const int tid  = threadIdx.x;
    const int wid  = tid >> 5;
    const int lane = tid & 31;

    if (do_cls) {
        for (int i = tid; i < CPH * OUTC; i += 256) s_wc[i] = wc[i];
        if (tid < OUTC) s_bc[tid] = bc[tid];
        __syncthreads();
    }

    int n = nbase + ((blockIdx.x * blockDim.x + tid) >> 5);
    if (n >= nend) return;
    const int beg = g_off[n];
    const int end = (n + 1 < N) ? g_off[n + 1] : E;

    // fp16 Q: 4 halves per lane
    float4 q;
    {
        uint2 u = *(const uint2*)(Q + (size_t)n * FDIM + lane * 4);
        float2 f0 = __half22float2(*(const __half2*)&u.x);
        float2 f1 = __half22float2(*(const __half2*)&u.y);
        q = make_float4(f0.x, f0.y, f1.x, f1.y);
    }

    float den = 0.f;
    float a0 = 0.f, a1 = 0.f, a2 = 0.f, a3 = 0.f;
    const float scale = 0.17677669529663687f;  // 1/sqrt(32)

    for (int base = beg; base < end; base += 32) {
        int myidx = (base + lane < end) ? g_csr_src[base + lane] : 0;
        int rem = end - base;
        int cnt = rem < 32 ? rem : 32;
        int j = 0;
        for (; j + 3 < cnt; j += 4) {
            int s0 = __shfl_sync(0xffffffffu, myidx, j);
            int s1 = __shfl_sync(0xffffffffu, myidx, j + 1);
            int s2 = __shfl_sync(0xffffffffu, myidx, j + 2);
            int s3 = __shfl_sync(0xffffffffu, myidx, j + 3);
            uint4 r0 = *(const uint4*)(KV + (size_t)s0 * 256 + lane * 8);
            uint4 r1 = *(const uint4*)(KV + (size_t)s1 * 256 + lane * 8);
            uint4 r2 = *(const uint4*)(KV + (size_t)s2 * 256 + lane * 8);
            uint4 r3 = *(const uint4*)(KV + (size_t)s3 * 256 + lane * 8);
            float4 k0 = unpack_lo(r0), k1 = unpack_lo(r1);
            float4 k2 = unpack_lo(r2), k3 = unpack_lo(r3);
            float d0 = q.x * k0.x + q.y * k0.y + q.z * k0.z + q.w * k0.w;
            float d1 = q.x * k1.x + q.y * k1.y + q.z * k1.z + q.w * k1.w;
            float d2 = q.x * k2.x + q.y * k2.y + q.z * k2.z + q.w * k2.w;
            float d3 = q.x * k3.x + q.y * k3.y + q.z * k3.z + q.w * k3.w;
            d0 += __shfl_xor_sync(0xffffffffu, d0, 4);
            d1 += __shfl_xor_sync(0xffffffffu, d1, 4);
            d2 += __shfl_xor_sync(0xffffffffu, d2, 4);
            d3 += __shfl_xor_sync(0xffffffffu, d3, 4);
            d0 += __shfl_xor_sync(0xffffffffu, d0, 2);
            d1 += __shfl_xor_sync(0xffffffffu, d1, 2);
            d2 += __shfl_xor_sync(0xffffffffu, d2, 2);
            d3 += __shfl_xor_sync(0xffffffffu, d3, 2);
            d0 += __shfl_xor_sync(0xffffffffu, d0, 1);
            d1 += __shfl_xor_sync(0xffffffffu, d1, 1);
            d2 += __shfl_xor_sync(0xffffffffu, d2, 1);
            d3 += __shfl_xor_sync(0xffffffffu, d3, 1);
            float w0 = __expf(d0 * scale);
            float w1 = __expf(d1 * scale);
            float w2 = __expf(d2 * scale);
            float w3 = __expf(d3 * scale);
            den += (w0 + w1) + (w2 + w3);
            float4 v0 = unpack_hi(r0), v1 = unpack_hi(r1);
            float4 v2 = unpack_hi(r2), v3 = unpack_hi(r3);
            a0 = fmaf(w0, v0.x, fmaf(w1, v1.x, fmaf(w2, v2.x, fmaf(w3, v3.x, a0))));
            a1 = fmaf(w0, v0.y, fmaf(w1, v1.y, fmaf(w2, v2.y, fmaf(w3, v3.y, a1))));
            a2 = fmaf(w0, v0.z, fmaf(w1, v1.z, fmaf(w2, v2.z, fmaf(w3, v3.z, a2))));
            a3 = fmaf(w0, v0.w, fmaf(w1, v1.w, fmaf(w2, v2.w, fmaf(w3, v3.w, a3))));
        }
        for (; j < cnt; j++) {
            int s0 = __shfl_sync(0xffffffffu, myidx, j);
            uint4 r0 = *(const uint4*)(KV + (size_t)s0 * 256 + lane * 8);
            float4 k0 = unpack_lo(r0);
            float4 v0 = unpack_hi(r0);
            float d0 = q.x * k0.x + q.y * k0.y + q.z * k0.z + q.w * k0.w;
            d0 += __shfl_xor_sync(0xffffffffu, d0, 4);
            d0 += __shfl_xor_sync(0xffffffffu, d0, 2);
            d0 += __shfl_xor_sync(0xffffffffu, d0, 1);
            float w0 = __expf(d0 * scale);
            den += w0;
            a0 = fmaf(w0, v0.x, a0);
            a1 = fmaf(w0, v0.y, a1);
            a2 = fmaf(w0, v0.z, a2);
            a3 = fmaf(w0, v0.w, a3);
        }
    }

    const float rden = 1.f / (den + 1e-16f);
    a0 *= rden; a1 *= rden; a2 *= rden; a3 *= rden;

    // head mean: sum over 4 heads (lanes l, l^8, l^16, l^24 share channels)
    #pragma unroll
    for (int dd = 8; dd <= 16; dd <<= 1) {
        a0 += __shfl_xor_sync(0xffffffffu, a0, dd);
        a1 += __shfl_xor_sync(0xffffffffu, a1, dd);
        a2 += __shfl_xor_sync(0xffffffffu, a2, dd);
        a3 += __shfl_xor_sync(0xffffffffu, a3, dd);
    }

    if (lane < 8) {
        float4 sk = *(const float4*)(skip + (size_t)n * CPH + lane * 4);
        float4 o;
        o.x = fmaxf(a0 * 0.25f + sk.x, 0.f);
        o.y = fmaxf(a1 * 0.25f + sk.y, 0.f);
        o.z = fmaxf(a2 * 0.25f + sk.z, 0.f);
        o.w = fmaxf(a3 * 0.25f + sk.w, 0.f);
        if (!do_cls) {
            uint2 u;
            *(__half2*)&u.x = __floats2half2_rn(o.x, o.y);
            *(__half2*)&u.y = __floats2half2_rn(o.z, o.w);
            *(uint2*)(out_h + (size_t)n * CPH + lane * 4) = u;
        } else {
            *(float4*)&s_h[wid][lane * 4] = o;
        }
    }

    if (do_cls) {
        __syncwarp();
        const float* h = s_h[wid];
        int c2 = 32 + (lane & 7);
        float acc1 = s_bc[lane];
        float acc2 = s_bc[c2];
        #pragma unroll 8
        for (int j = 0; j < CPH; j++) {
            float hv = h[j];
            acc1 = fmaf(hv, s_wc[j * OUTC + lane], acc1);
            acc2 = fmaf(hv, s_wc[j * OUTC + c2], acc2);
        }
        out_f[(size_t)n * OUTC + lane] = acc1;
        if (lane < 8) out_f[(size_t)n * OUTC + c2] = acc2;
    }
}

// ---------------------------------------------------------------------------
// Host orchestration
// ---------------------------------------------------------------------------
static inline unsigned int ceil_div(unsigned int a, unsigned int b) { return (a + b - 1) / b; }

extern "C" void kernel_launch(void* const* d_in, const int* in_sizes, int n_in,
                              void* d_out, int out_size) {
    const float* x   = (const float*)d_in[0];
    const void*  ei  = d_in[1];
    const float* wq1 = (const float*)d_in[2];
    const float* bq1 = (const float*)d_in[3];
    const float* wk1 = (const float*)d_in[4];
    const float* bk1 = (const float*)d_in[5];
    const float* wv1 = (const float*)d_in[6];
    const float* bv1 = (const float*)d_in[7];
    const float* ws1 = (const float*)d_in[8];
    const float* bs1 = (const float*)d_in[9];
    const float* wq2 = (const float*)d_in[10];
    const float* bq2 = (const float*)d_in[11];
    const float* wk2 = (const float*)d_in[12];
    const float* bk2 = (const float*)d_in[13];
    const float* wv2 = (const float*)d_in[14];
    const float* bv2 = (const float*)d_in[15];
    const float* ws2 = (const float*)d_in[16];
    const float* bs2 = (const float*)d_in[17];
    const float* wc  = (const float*)d_in[18];
    const float* bc  = (const float*)d_in[19];

    const int N = in_sizes[0] / FDIM;   // x is [N,128]
    const int E = in_sizes[1] / 2;      // edge_index is [2,E]

    float  *skipp;
    __half *Qp, *KVp, *h1p;
    cudaGetSymbolAddress((void**)&Qp,    g_Q);
    cudaGetSymbolAddress((void**)&KVp,   g_KV);
    cudaGetSymbolAddress((void**)&skipp, g_skip);
    cudaGetSymbolAddress((void**)&h1p,   g_h1);

    static cudaStream_t s_pre = nullptr;
    static cudaEvent_t  ev_fork = nullptr, ev_join = nullptr;
    static cudaEvent_t  ev_a0 = nullptr, ev_g0 = nullptr;
    if (s_pre == nullptr) {
        cudaStreamCreate(&s_pre);
        cudaEventCreateWithFlags(&ev_fork, cudaEventDisableTiming);
        cudaEventCreateWithFlags(&ev_join, cudaEventDisableTiming);
        cudaEventCreateWithFlags(&ev_a0, cudaEventDisableTiming);
        cudaEventCreateWithFlags(&ev_g0, cudaEventDisableTiming);
    }

    const int NB = (N + SCAN_B - 1) / SCAN_B;
    int Nh = ((N / 2 + 127) / 128) * 128;
    if (Nh > N) Nh = N;
    const int detect_pairs = (E < 65536) ? E : 65536;

    // fork: CSR build on s_pre, concurrent with layer-1 GEMM
    cudaEventRecord(ev_fork, 0);
    cudaStreamWaitEvent(s_pre, ev_fork, 0);
    init_pre_kernel<<<ceil_div((unsigned)N, 256u), 256, 0, s_pre>>>(N);
    detect_dtype_kernel<<<ceil_div((unsigned)detect_pairs, 256u), 256, 0, s_pre>>>(
        (const uint2*)ei, detect_pairs);
    hist_kernel<<<ceil_div((unsigned)E, 256u), 256, 0, s_pre>>>(ei, E);
    scan_p1_kernel<<<NB, SCAN_B, 0, s_pre>>>(N);
    scan_p2_kernel<<<1, SCAN_B, 0, s_pre>>>(NB);
    scan_p3_kernel<<<NB, SCAN_B, 0, s_pre>>>(N);
    scatter_kernel<<<ceil_div((unsigned)E, 256u), 256, 0, s_pre>>>(ei, E);
    cudaEventRecord(ev_join, s_pre);

    // layer-1 projections (fp32 input) overlap with prepro
    hmma_qkvs_kernel<<<ceil_div((unsigned)N, 128u), 256>>>(
        x, 0, wq1, wk1, wv1, ws1, bq1, bk1, bv1, bs1, Qp, KVp, skipp, 0, N, FDIM);

    cudaStreamWaitEvent(0, ev_join, 0);

    // layer-1 attention chunk 0; gemm2(chunk0) overlaps attn1(chunk1)
    attn_fused_kernel<<<ceil_div((unsigned)Nh, 8u), 256>>>(
        Qp, KVp, skipp, h1p, nullptr, wc, bc, 0, 0, Nh, N, E);
    cudaEventRecord(ev_a0, 0);

    cudaStreamWaitEvent(s_pre, ev_a0, 0);
    hmma_qkvs_kernel<<<ceil_div((unsigned)Nh, 128u), 256, 0, s_pre>>>(
        h1p, 1, wq2, wk2, wv2, ws2, bq2, bk2, bv2, bs2, Qp, KVp, skipp, 0, N, CPH);
    cudaEventRecord(ev_g0, s_pre);

    if (Nh < N)
        attn_fused_kernel<<<ceil_div((unsigned)(N - Nh), 8u), 256>>>(
            Qp, KVp, skipp, h1p, nullptr, wc, bc, 0, Nh, N, N, E);

    if (Nh < N)
        hmma_qkvs_kernel<<<ceil_div((unsigned)(N - Nh), 128u), 256>>>(
            h1p, 1, wq2, wk2, wv2, ws2, bq2, bk2, bv2, bs2, Qp, KVp, skipp, Nh, N, CPH);

    // layer-2 attention with fused classifier
    cudaStreamWaitEvent(0, ev_g0, 0);
    attn_fused_kernel<<<ceil_div((unsigned)N, 8u), 256>>>(
        Qp, KVp, skipp, nullptr, (float*)d_out, wc, bc, 1, 0, N, N, E);
}